// round 13
// baseline (speedup 1.0000x reference)
#include <cuda_runtime.h>
#include <cuda_fp16.h>

#define B_ 4
#define S_ 2048
#define H_ 8
#define DM_ 512
#define L2E 1.4426950408889634f

// ---------------- device scratch (no cudaMalloc allowed) ----------------
__device__ __half g_qh[B_ * S_ * DM_];           // query, fp16
__device__ __half g_wh[3 * DM_ * DM_];           // in_proj_weight, fp16
__device__ __half g_woh[DM_ * DM_];              // out_w, fp16
__device__ __half g_q[B_ * H_ * S_ * 64];        // [B*H][S][D], pre-scaled 0.125*log2e
__device__ __half g_k[B_ * H_ * S_ * 64];        // [B*H][S][D]
__device__ __half g_vt[B_ * H_ * 64 * S_];       // [B*H][D][S]  (transposed)
// g_bias: [B][S][32 tiles][64 slots], slot(k) = (k&7)*8 + (k>>3)  (fragment order)
__device__ __half g_bias[(size_t)B_ * S_ * S_];
__device__ __half g_ctxh[B_ * S_ * DM_];         // [B][S][DM]
__device__ int g_scol[B_ * S_];                  // sorted gene columns (ascending)
__device__ unsigned short g_sperm[B_ * S_];      // sorted slot -> original key index

// ---------------- helpers ----------------
__device__ __forceinline__ void mma16(float* d, const unsigned* a, unsigned b0, unsigned b1) {
    asm volatile(
        "mma.sync.aligned.m16n8k16.row.col.f32.f16.f16.f32 "
        "{%0,%1,%2,%3},{%4,%5,%6,%7},{%8,%9},{%0,%1,%2,%3};"
        : "+f"(d[0]), "+f"(d[1]), "+f"(d[2]), "+f"(d[3])
        : "r"(a[0]), "r"(a[1]), "r"(a[2]), "r"(a[3]), "r"(b0), "r"(b1));
}
__device__ __forceinline__ void ldsm4(unsigned& r0, unsigned& r1, unsigned& r2, unsigned& r3,
                                      unsigned a) {
    asm volatile("ldmatrix.sync.aligned.m8n8.x4.shared.b16 {%0,%1,%2,%3}, [%4];"
                 : "=r"(r0), "=r"(r1), "=r"(r2), "=r"(r3) : "r"(a));
}
__device__ __forceinline__ unsigned packh2(float x, float y) {
    __half2 h = __floats2half2_rn(x, y);
    return *(unsigned*)&h;
}
__device__ __forceinline__ unsigned h2exp2(unsigned x) {
    unsigned r;
    asm("ex2.approx.f16x2 %0, %1;" : "=r"(r) : "r"(x));
    return r;
}
__device__ __forceinline__ unsigned sptr(const void* p) {
    return (unsigned)__cvta_generic_to_shared(p);
}
__device__ __forceinline__ void cpa16(unsigned s, const void* g) {
    asm volatile("cp.async.cg.shared.global [%0], [%1], 16;" :: "r"(s), "l"(g));
}
#define CP_COMMIT() asm volatile("cp.async.commit_group;")
#define CP_WAIT0()  asm volatile("cp.async.wait_group 0;")

// ============================================================
// Kernel 0: fused fp32->fp16 convert (1280 blocks) + per-batch gene sort
// (4 blocks).  Sort output is used ONLY to reorder gather loads; all data
// layouts stay identical to the unsorted version.
// ============================================================
#define NQ4 (B_ * S_ * DM_ / 4)
#define NW4 (3 * DM_ * DM_ / 4)
#define NO4 (DM_ * DM_ / 4)
#define CVT_BLKS 1280
__global__ __launch_bounds__(256) void cvt3_sort_kernel(
    const float4* __restrict__ q, const float4* __restrict__ w,
    const float4* __restrict__ wo, const int* __restrict__ gi)
{
    __shared__ unsigned keys[2048];
    const int tid = threadIdx.x;

    if (blockIdx.x >= CVT_BLKS) {
        // ---------------- sort role ----------------
        const int b = blockIdx.x - CVT_BLKS;
        for (int i = tid; i < 2048; i += 256)
            keys[i] = ((unsigned)gi[b * 2048 + i] << 11) | (unsigned)i;
        for (int k = 2; k <= 2048; k <<= 1) {
            for (int j = k >> 1; j > 0; j >>= 1) {
                __syncthreads();
#pragma unroll
                for (int i = tid; i < 2048; i += 256) {
                    const int ixj = i ^ j;
                    if (ixj > i) {
                        const unsigned a = keys[i], c = keys[ixj];
                        const bool up = ((i & k) == 0);
                        if (up ? (a > c) : (a < c)) { keys[i] = c; keys[ixj] = a; }
                    }
                }
            }
        }
        __syncthreads();
        for (int i = tid; i < 2048; i += 256) {
            const unsigned key = keys[i];
            g_scol[b * 2048 + i] = (int)(key >> 11);
            g_sperm[b * 2048 + i] = (unsigned short)(key & 2047u);
        }
        return;
    }

    // ---------------- convert role ----------------
    for (int i = blockIdx.x * 256 + tid; i < NQ4 + NW4 + NO4; i += CVT_BLKS * 256) {
        const float4* src;
        uint2* dst;
        int j = i;
        if (j < NQ4) { src = q; dst = (uint2*)g_qh; }
        else if ((j -= NQ4) < NW4) { src = w; dst = (uint2*)g_wh; }
        else { j -= NW4; src = wo; dst = (uint2*)g_woh; }
        float4 v = src[j];
        dst[j] = make_uint2(packh2(v.x, v.y), packh2(v.z, v.w));
    }
}

// ============================================================
// Kernel 1 (fused): QKV projection + gene bias gather, interleaved roles.
// 2816 blocks: id%11<3 -> qkv (768 blocks), else gather (2048 blocks x 4 rows).
// Gather: loads walk SORTED gene columns (adjacent lanes -> adjacent genes ->
// L2 sector merging, ~2.3x fewer requests), unscatter via smem staging into
// the SAME fragment-order bias layout as before.
// ============================================================
__global__ __launch_bounds__(256) void qkv_gather_kernel(
    const float* __restrict__ bias,
    const int* __restrict__ gi, const float* __restrict__ gb)
{
    __shared__ __align__(16) __half As[2][128 * 40];
    __shared__ __align__(16) __half Bs[2][128 * 40];

    const int id = blockIdx.x;
    const int grp = id / 11, rem = id % 11;

    if (rem >= 3) {
        // ---------------- gather role ----------------
        const int gid = grp * 8 + (rem - 3);  // 0..2047
        const int b = gid >> 9;
        const int qbase = (gid & 511) * 4;
        const int tid = threadIdx.x;
        int* scol = (int*)&As[0][0];                              // 8192 B
        unsigned short* sperm = (unsigned short*)&Bs[0][0];       // 4096 B
        __half* stage = (__half*)((char*)&Bs[0][0] + 4096);       // 4096 B
        for (int i = tid; i < 2048; i += 256) {
            scol[i] = g_scol[b * 2048 + i];
            sperm[i] = g_sperm[b * 2048 + i];
        }
        __syncthreads();
#pragma unroll
        for (int q = 0; q < 4; q++) {
            const float* src = gb + (size_t)gi[b * 2048 + qbase + q] * 8192;
#pragma unroll
            for (int j = tid; j < 2048; j += 256) {
                const float v = src[scol[j]] * L2E;
                const int k = sperm[j];
                // fragment slot within the 64-key tile: (k&7)*8 + ((k&63)>>3)
                const int slot = (k & ~63) + ((k & 7) << 3) + ((k & 63) >> 3);
                stage[slot] = __float2half_rn(v);
            }
            __syncthreads();
            __half* drow = g_bias + ((size_t)(b * 2048 + qbase + q)) * 2048;
            ((uint4*)drow)[tid] = ((const uint4*)stage)[tid];
            __syncthreads();
        }
        return;
    }

    // ---------------- qkv role ----------------
    const int qid = grp * 3 + rem;  // 0..767
    const int bm = (qid / 12) * 128;
    const int bn = (qid % 12) * 128;
    const __half* __restrict__ A = g_qh;
    const __half* __restrict__ W = g_wh;
    const int tid = threadIdx.x;
    const int w = tid >> 5, lane = tid & 31;
    const int g = lane >> 2, c = lane & 3;
    const int wm = (w >> 2) * 64, wn = (w & 3) * 32;

    const int srow = tid >> 2, sh = (tid & 3) * 8;
    const int arow = wm + (lane & 15);
    const int acol8 = (lane >> 4) << 3;
    const int brow = wn + ((lane >> 4) << 3) + (lane & 7);
    const int bcol8 = ((lane >> 3) & 1) << 3;

    float acc[4][4][4];
#pragma unroll
    for (int nb = 0; nb < 4; nb++) {
        const int n = bn + wn + nb * 8 + 2 * c;
        const float b0 = bias[n], b1 = bias[n + 1];
#pragma unroll
        for (int mb = 0; mb < 4; mb++) {
            acc[mb][nb][0] = b0; acc[mb][nb][1] = b1;
            acc[mb][nb][2] = b0; acc[mb][nb][3] = b1;
        }
    }

    {
        unsigned sa = sptr(&As[0][0]), sb = sptr(&Bs[0][0]);
        cpa16(sa + (srow * 40 + sh) * 2, &A[(size_t)(bm + srow) * 512 + sh]);
        cpa16(sa + ((srow + 64) * 40 + sh) * 2, &A[(size_t)(bm + srow + 64) * 512 + sh]);
        cpa16(sb + (srow * 40 + sh) * 2, &W[(size_t)(bn + srow) * 512 + sh]);
        cpa16(sb + ((srow + 64) * 40 + sh) * 2, &W[(size_t)(bn + srow + 64) * 512 + sh]);
        CP_COMMIT();
    }

    for (int t = 0; t < 16; t++) {
        CP_WAIT0();
        __syncthreads();
        const int buf = t & 1;
        if (t + 1 < 16) {
            const int kt = (t + 1) * 32;
            unsigned sa = sptr(&As[buf ^ 1][0]), sb = sptr(&Bs[buf ^ 1][0]);
            cpa16(sa + (srow * 40 + sh) * 2, &A[(size_t)(bm + srow) * 512 + kt + sh]);
            cpa16(sa + ((srow + 64) * 40 + sh) * 2, &A[(size_t)(bm + srow + 64) * 512 + kt + sh]);
            cpa16(sb + (srow * 40 + sh) * 2, &W[(size_t)(bn + srow) * 512 + kt + sh]);
            cpa16(sb + ((srow + 64) * 40 + sh) * 2, &W[(size_t)(bn + srow + 64) * 512 + kt + sh]);
            CP_COMMIT();
        }
        const __half* as = As[buf];
        const __half* bs = Bs[buf];
#pragma unroll
        for (int ks = 0; ks < 2; ks++) {
            unsigned a[4][4];
#pragma unroll
            for (int mb = 0; mb < 4; mb++)
                ldsm4(a[mb][0], a[mb][1], a[mb][2], a[mb][3],
                      sptr(&as[(arow + mb * 16) * 40 + ks * 16 + acol8]));
            unsigned bb[4][2];
#pragma unroll
            for (int p = 0; p < 2; p++)
                ldsm4(bb[2 * p][0], bb[2 * p][1], bb[2 * p + 1][0], bb[2 * p + 1][1],
                      sptr(&bs[(brow + p * 16) * 40 + ks * 16 + bcol8]));
#pragma unroll
            for (int nb = 0; nb < 4; nb++)
#pragma unroll
                for (int mb = 0; mb < 4; mb++)
                    mma16(acc[mb][nb], a[mb], bb[nb][0], bb[nb][1]);
        }
    }

    const int part = bn >> 9;  // 0=Q 1=K 2=V (uniform per block)
    if (part < 2) {
        __half* dst = part ? g_k : g_q;
        const float sc = part ? 1.0f : 0.125f * L2E;
#pragma unroll
        for (int mb = 0; mb < 4; mb++) {
            const int m0 = bm + wm + mb * 16 + g;
            const int bb0 = m0 >> 11, s0 = m0 & 2047;
            const int bb1 = (m0 + 8) >> 11, s1 = (m0 + 8) & 2047;
#pragma unroll
            for (int nb = 0; nb < 4; nb++) {
                const int n = bn + wn + nb * 8 + 2 * c;
                const int h = (n >> 6) & 7;
                const int d = n & 63;
                *(unsigned*)&dst[((size_t)((bb0 * 8 + h) * 2048 + s0)) * 64 + d] =
                    packh2(acc[mb][nb][0] * sc, acc[mb][nb][1] * sc);
                *(unsigned*)&dst[((size_t)((bb1 * 8 + h) * 2048 + s1)) * 64 + d] =
                    packh2(acc[mb][nb][2] * sc, acc[mb][nb][3] * sc);
            }
        }
    } else {
#pragma unroll
        for (int mb = 0; mb < 4; mb++) {
            const int m0 = bm + wm + mb * 16 + g;
            const int bb0 = m0 >> 11, s0 = m0 & 2047;
            const int bb1 = (m0 + 8) >> 11, s1 = (m0 + 8) & 2047;
#pragma unroll
            for (int nb = 0; nb < 4; nb++) {
                const int n = bn + wn + nb * 8 + 2 * c;
                const int h = (n >> 6) & 7;
                const int d = n & 63;
                __half* p0 = &g_vt[((size_t)((bb0 * 8 + h) * 64 + d)) * 2048];
                __half* p1 = &g_vt[((size_t)((bb1 * 8 + h) * 64 + d)) * 2048];
                p0[s0] = __float2half_rn(acc[mb][nb][0]);
                p0[2048 + s0] = __float2half_rn(acc[mb][nb][1]);
                p1[s1] = __float2half_rn(acc[mb][nb][2]);
                p1[2048 + s1] = __float2half_rn(acc[mb][nb][3]);
            }
        }
    }
}

// ============================================================
// Kernel 3: flash attention (identical to R11 best).
// Bias in fragment order -> 4 x LDG.128 per thread per tile.
// Softmax: fixed max=0, f16x2 exp2, row sums via ones-mma.
// ============================================================
#define ONES2 0x3C003C00u
__global__ __launch_bounds__(256) void attn_kernel()
{
    __shared__ __align__(16) __half Ks[2][64 * 72];
    __shared__ __align__(16) __half Vts[2][64 * 72];

    const int qt = blockIdx.x, h = blockIdx.y, b = blockIdx.z;
    const int tid = threadIdx.x;
    const int w = tid >> 5, lane = tid & 31;
    const int g = lane >> 2, c = lane & 3;

    const size_t bh = (size_t)(b * 8 + h);
    const __half* Qg = g_q + bh * 2048 * 64;
    const __half* Kg = g_k + bh * 2048 * 64;
    const __half* Vtg = g_vt + bh * 64 * 2048;
    const __half* Bg = g_bias + ((size_t)b * 2048 + qt * 128) * 2048;

    const int srow = tid >> 3, sh = (tid & 7) * 8;
    const int lrow = ((lane >> 4) << 3) + (lane & 7);
    const int lcol8 = ((lane >> 3) & 1) << 3;

    unsigned qA[4][4];
    {
        const int r0 = qt * 128 + 16 * w + g;
#pragma unroll
        for (int kb = 0; kb < 4; kb++) {
            qA[kb][0] = *(const unsigned*)&Qg[(size_t)r0 * 64 + kb * 16 + 2 * c];
            qA[kb][1] = *(const unsigned*)&Qg[(size_t)(r0 + 8) * 64 + kb * 16 + 2 * c];
            qA[kb][2] = *(const unsigned*)&Qg[(size_t)r0 * 64 + kb * 16 + 2 * c + 8];
            qA[kb][3] = *(const unsigned*)&Qg[(size_t)(r0 + 8) * 64 + kb * 16 + 2 * c + 8];
        }
    }

    float o[8][4];
#pragma unroll
    for (int nb = 0; nb < 8; nb++)
#pragma unroll
        for (int i = 0; i < 4; i++) o[nb][i] = 0.f;
    float lacc[4] = {0.f, 0.f, 0.f, 0.f};

    const __half* Bt0 = Bg + (size_t)(16 * w + g) * 2048 + 16 * c;
    const __half* Bt1 = Bt0 + 8 * 2048;

    {
        unsigned sk = sptr(&Ks[0][0]), sv = sptr(&Vts[0][0]);
        cpa16(sk + (srow * 72 + sh) * 2, &Kg[(size_t)srow * 64 + sh]);
        cpa16(sk + ((srow + 32) * 72 + sh) * 2, &Kg[(size_t)(srow + 32) * 64 + sh]);
        cpa16(sv + (srow * 72 + sh) * 2, &Vtg[(size_t)srow * 2048 + sh]);
        cpa16(sv + ((srow + 32) * 72 + sh) * 2, &Vtg[(size_t)(srow + 32) * 2048 + sh]);
        CP_COMMIT();
    }

    for (int t = 0; t < 32; t++) {
        float s[8][4];
        {
            uint4 lo0 = *(const uint4*)&Bt0[t * 64];
            uint4 hi0 = *(const uint4*)&Bt0[t * 64 + 8];
            uint4 lo1 = *(const uint4*)&Bt1[t * 64];
            uint4 hi1 = *(const uint4*)&Bt1[t * 64 + 8];
            const __half2* L0 = (const __half2*)&lo0;
            const __half2* H0 = (const __half2*)&hi0;
            const __half2* L1 = (const __half2*)&lo1;
            const __half2* H1 = (const __half2*)&hi1;
#pragma unroll
            for (int p = 0; p < 4; p++) {
                float2 a = __half22float2(L0[p]);
                float2 bq = __half22float2(H0[p]);
                float2 cc = __half22float2(L1[p]);
                float2 dd = __half22float2(H1[p]);
                s[2 * p][0] = a.x;  s[2 * p + 1][0] = a.y;
                s[2 * p][1] = bq.x; s[2 * p + 1][1] = bq.y;
                s[2 * p][2] = cc.x; s[2 * p + 1][2] = cc.y;
                s[2 * p][3] = dd.x; s[2 * p + 1][3] = dd.y;
            }
        }

        CP_WAIT0();
        __syncthreads();
        const int buf = t & 1;
        if (t + 1 < 32) {
            unsigned sk = sptr(&Ks[buf ^ 1][0]), sv = sptr(&Vts[buf ^ 1][0]);
            const __half* Kn = Kg + (size_t)(t + 1) * 64 * 64;
            const __half* Vn = Vtg + (size_t)(t + 1) * 64;
            cpa16(sk + (srow * 72 + sh) * 2, &Kn[(size_t)srow * 64 + sh]);
            cpa16(sk + ((srow + 32) * 72 + sh) * 2, &Kn[(size_t)(srow + 32) * 64 + sh]);
            cpa16(sv + (srow * 72 + sh) * 2, &Vn[(size_t)srow * 2048 + sh]);
            cpa16(sv + ((srow + 32) * 72 + sh) * 2, &Vn[(size_t)(srow + 32) * 2048 + sh]);
            CP_COMMIT();
        }
        const __half* ks_ = Ks[buf];
        const __half* vs_ = Vts[buf];

#pragma unroll
        for (int kb = 0; kb < 4; kb++) {
#pragma unroll
            for (int j = 0; j < 4; j++) {
                unsigned b00, b01, b10, b11;
                ldsm4(b00, b01, b10, b11,
                      sptr(&ks_[(j * 16 + lrow) * 72 + kb * 16 + lcol8]));
                mma16(s[2 * j], qA[kb], b00, b01);
                mma16(s[2 * j + 1], qA[kb], b10, b11);
            }
        }

        unsigned pa[4][4];
#pragma unroll
        for (int kb = 0; kb < 4; kb++) {
            pa[kb][0] = h2exp2(packh2(s[2 * kb][0], s[2 * kb][1]));
            pa[kb][1] = h2exp2(packh2(s[2 * kb][2], s[2 * kb][3]));
            pa[kb][2] = h2exp2(packh2(s[2 * kb + 1][0], s[2 * kb + 1][1]));
            pa[kb][3] = h2exp2(packh2(s[2 * kb + 1][2], s[2 * kb + 1][3]));
        }

#pragma unroll
        for (int kb = 0; kb < 4; kb++)
            mma16(lacc, pa[kb], ONES2, ONES2);

#pragma unroll
        for (int kb = 0; kb < 4; kb++) {
#pragma unroll
            for (int j = 0; j < 4; j++) {
                unsigned b00, b01, b10, b11;
                ldsm4(b00, b01, b10, b11,
                      sptr(&vs_[(j * 16 + lrow) * 72 + kb * 16 + lcol8]));
                mma16(o[2 * j], pa[kb], b00, b01);
                mma16(o[2 * j + 1], pa[kb], b10, b11);
            }
        }
    }

    const float inv0 = 1.f / lacc[0], inv1 = 1.f / lacc[2];
    const int row0 = b * 2048 + qt * 128 + 16 * w + g;
#pragma unroll
    for (int nb = 0; nb < 8; nb++) {
        const int d = h * 64 + nb * 8 + 2 * c;
        *(unsigned*)&g_ctxh[(size_t)row0 * 512 + d] =
            packh2(o[nb][0] * inv0, o[nb][1] * inv0);
        *(unsigned*)&g_ctxh[(size_t)(row0 + 8) * 512 + d] =
            packh2(o[nb][2] * inv1, o[nb][3] * inv1);
    }
}

// ============================================================
// Kernel 4: output projection, 64x128 tiles (512 blocks for occupancy).
// ============================================================
__global__ __launch_bounds__(256) void out_gemm_kernel(
    const float* __restrict__ ob, float* __restrict__ C)
{
    __shared__ __align__(16) __half As[2][64 * 40];
    __shared__ __align__(16) __half Bs[2][128 * 40];
    const __half* __restrict__ A = g_ctxh;
    const __half* __restrict__ W = g_woh;
    const int bm = blockIdx.y * 64;
    const int bn = blockIdx.x * 128;
    const int tid = threadIdx.x;
    const int w = tid >> 5, lane = tid & 31;
    const int g = lane >> 2, c = lane & 3;
    const int wm = (w >> 2) * 32, wn = (w & 3) * 32;

    const int srow = tid >> 2, sh = (tid & 3) * 8;
    const int arow = wm + (lane & 15);
    const int acol8 = (lane >> 4) << 3;
    const int brow = wn + ((lane >> 4) << 3) + (lane & 7);
    const int bcol8 = ((lane >> 3) & 1) << 3;

    float acc[2][4][4];
#pragma unroll
    for (int nb = 0; nb < 4; nb++) {
        const int n = bn + wn + nb * 8 + 2 * c;
        const float b0 = ob[n], b1 = ob[n + 1];
#pragma unroll
        for (int mb = 0; mb < 2; mb++) {
            acc[mb][nb][0] = b0; acc[mb][nb][1] = b1;
            acc[mb][nb][2] = b0; acc[mb][nb][3] = b1;
        }
    }

    {
        unsigned sa = sptr(&As[0][0]), sb = sptr(&Bs[0][0]);
        cpa16(sa + (srow * 40 + sh) * 2, &A[(size_t)(bm + srow) * 512 + sh]);
        cpa16(sb + (srow * 40 + sh) * 2, &W[(size_t)(bn + srow) * 512 + sh]);
        cpa16(sb + ((srow + 64) * 40 + sh) * 2, &W[(size_t)(bn + srow + 64) * 512 + sh]);
        CP_COMMIT();
    }

    for (int t = 0; t < 16; t++) {
        CP_WAIT0();
        __syncthreads();
        const int buf = t & 1;
        if (t + 1 < 16) {
            const int kt = (t + 1) * 32;
            unsigned sa = sptr(&As[buf ^ 1][0]), sb = sptr(&Bs[buf ^ 1][0]);
            cpa16(sa + (srow * 40 + sh) * 2, &A[(size_t)(bm + srow) * 512 + kt + sh]);
            cpa16(sb + (srow * 40 + sh) * 2, &W[(size_t)(bn + srow) * 512 + kt + sh]);
            cpa16(sb + ((srow + 64) * 40 + sh) * 2, &W[(size_t)(bn + srow + 64) * 512 + kt + sh]);
            CP_COMMIT();
        }
        const __half* as = As[buf];
        const __half* bs = Bs[buf];
#pragma unroll
        for (int ks = 0; ks < 2; ks++) {
            unsigned a[2][4];
#pragma unroll
            for (int mb = 0; mb < 2; mb++)
                ldsm4(a[mb][0], a[mb][1], a[mb][2], a[mb][3],
                      sptr(&as[(arow + mb * 16) * 40 + ks * 16 + acol8]));
            unsigned bb[4][2];
#pragma unroll
            for (int p = 0; p < 2; p++)
                ldsm4(bb[2 * p][0], bb[2 * p][1], bb[2 * p + 1][0], bb[2 * p + 1][1],
                      sptr(&bs[(brow + p * 16) * 40 + ks * 16 + bcol8]));
#pragma unroll
            for (int nb = 0; nb < 4; nb++)
#pragma unroll
                for (int mb = 0; mb < 2; mb++)
                    mma16(acc[mb][nb], a[mb], bb[nb][0], bb[nb][1]);
        }
    }

#pragma unroll
    for (int mb = 0; mb < 2; mb++) {
        const int m0 = bm + wm + mb * 16 + g;
#pragma unroll
        for (int nb = 0; nb < 4; nb++) {
            const int n = bn + wn + nb * 8 + 2 * c;
            *(float2*)&C[(size_t)m0 * 512 + n] =
                make_float2(acc[mb][nb][0], acc[mb][nb][1]);
            *(float2*)&C[(size_t)(m0 + 8) * 512 + n] =
                make_float2(acc[mb][nb][2], acc[mb][nb][3]);
        }
    }
}

// ============================================================
extern "C" void kernel_launch(void* const* d_in, const int* in_sizes, int n_in,
                              void* d_out, int out_size)
{
    const float* query = (const float*)d_in[0];
    const int*   gidx  = (const int*)d_in[1];
    const float* ipw   = (const float*)d_in[2];
    const float* ipb   = (const float*)d_in[3];
    const float* outw  = (const float*)d_in[4];
    const float* outb  = (const float*)d_in[5];
    const float* gbias = (const float*)d_in[6];
    float* out = (float*)d_out;

    cvt3_sort_kernel<<<CVT_BLKS + 4, 256>>>((const float4*)query, (const float4*)ipw,
                                            (const float4*)outw, gidx);
    qkv_gather_kernel<<<2816, 256>>>(ipb, gidx, gbias);
    attn_kernel<<<dim3(16, 8, 4), 256>>>();
    out_gemm_kernel<<<dim3(4, 128), 256>>>(outb, out);
}

// round 14
// speedup vs baseline: 1.4684x; 1.4684x over previous
#include <cuda_runtime.h>
#include <cuda_fp16.h>

#define B_ 4
#define S_ 2048
#define H_ 8
#define DM_ 512
#define L2E 1.4426950408889634f

// ---------------- device scratch (no cudaMalloc allowed) ----------------
__device__ __half g_qh[B_ * S_ * DM_];           // query, fp16
__device__ __half g_wh[3 * DM_ * DM_];           // in_proj_weight, fp16
__device__ __half g_woh[DM_ * DM_];              // out_w, fp16
__device__ __half g_q[B_ * H_ * S_ * 64];        // [B*H][S][D], pre-scaled 0.125*log2e
__device__ __half g_k[B_ * H_ * S_ * 64];        // [B*H][S][D]
__device__ __half g_vt[B_ * H_ * 64 * S_];       // [B*H][D][S]  (transposed)
// g_bias: [B][S][32 tiles][64 slots], slot(k) = (k&7)*8 + (k>>3)  (fragment order)
__device__ __half g_bias[(size_t)B_ * S_ * S_];
__device__ __half g_ctxh[B_ * S_ * DM_];         // [B][S][DM]

// ---------------- helpers ----------------
__device__ __forceinline__ void mma16(float* d, const unsigned* a, unsigned b0, unsigned b1) {
    asm volatile(
        "mma.sync.aligned.m16n8k16.row.col.f32.f16.f16.f32 "
        "{%0,%1,%2,%3},{%4,%5,%6,%7},{%8,%9},{%0,%1,%2,%3};"
        : "+f"(d[0]), "+f"(d[1]), "+f"(d[2]), "+f"(d[3])
        : "r"(a[0]), "r"(a[1]), "r"(a[2]), "r"(a[3]), "r"(b0), "r"(b1));
}
__device__ __forceinline__ void ldsm4(unsigned& r0, unsigned& r1, unsigned& r2, unsigned& r3,
                                      unsigned a) {
    asm volatile("ldmatrix.sync.aligned.m8n8.x4.shared.b16 {%0,%1,%2,%3}, [%4];"
                 : "=r"(r0), "=r"(r1), "=r"(r2), "=r"(r3) : "r"(a));
}
__device__ __forceinline__ unsigned packh2(float x, float y) {
    __half2 h = __floats2half2_rn(x, y);
    return *(unsigned*)&h;
}
__device__ __forceinline__ unsigned h2exp2(unsigned x) {
    unsigned r;
    asm("ex2.approx.f16x2 %0, %1;" : "=r"(r) : "r"(x));
    return r;
}
__device__ __forceinline__ unsigned sptr(const void* p) {
    return (unsigned)__cvta_generic_to_shared(p);
}
__device__ __forceinline__ void cpa16(unsigned s, const void* g) {
    asm volatile("cp.async.cg.shared.global [%0], [%1], 16;" :: "r"(s), "l"(g));
}
#define CP_COMMIT() asm volatile("cp.async.commit_group;")
#define CP_WAIT0()  asm volatile("cp.async.wait_group 0;")
#define ONES2 0x3C003C00u   // half2(1.0, 1.0)

// ============================================================
// Kernel 0: fused fp32 -> fp16 convert for query / in_proj_w / out_w
// ============================================================
#define NQ4 (B_ * S_ * DM_ / 4)
#define NW4 (3 * DM_ * DM_ / 4)
#define NO4 (DM_ * DM_ / 4)
__global__ __launch_bounds__(256) void cvt3_kernel(
    const float4* __restrict__ q, const float4* __restrict__ w,
    const float4* __restrict__ wo)
{
    for (int i = blockIdx.x * 256 + threadIdx.x; i < NQ4 + NW4 + NO4;
         i += gridDim.x * 256) {
        const float4* src;
        uint2* dst;
        int j = i;
        if (j < NQ4) { src = q; dst = (uint2*)g_qh; }
        else if ((j -= NQ4) < NW4) { src = w; dst = (uint2*)g_wh; }
        else { j -= NW4; src = wo; dst = (uint2*)g_woh; }
        float4 v = src[j];
        dst[j] = make_uint2(packh2(v.x, v.y), packh2(v.z, v.w));
    }
}

// ============================================================
// Kernel 1 (fused): QKV projection + gene bias gather, interleaved roles.
// 2816 blocks: id%11<3 -> qkv (768 blocks), else gather (2048 blocks x 4 rows).
// Gather writes bias in fragment order: slot(k) = (k&7)*8 + (k>>3).
// ============================================================
__global__ __launch_bounds__(256) void qkv_gather_kernel(
    const float* __restrict__ bias,
    const int* __restrict__ gi, const float* __restrict__ gb)
{
    __shared__ __align__(16) __half As[2][128 * 40];
    __shared__ __align__(16) __half Bs[2][128 * 40];

    const int id = blockIdx.x;
    const int grp = id / 11, rem = id % 11;

    if (rem >= 3) {
        // ---------------- gather role ----------------
        const int gid = grp * 8 + (rem - 3);  // 0..2047
        const int b = gid >> 9;
        const int qbase = (gid & 511) * 4;
        int* cols = (int*)&As[0][0];
        for (int i = threadIdx.x; i < 2048; i += 256) cols[i] = gi[b * 2048 + i];
        __syncthreads();
        const int t = threadIdx.x >> 3;        // 64-key tile 0..31
        const int sg = threadIdx.x & 7;        // slot group (= k&7)
        const int* ct = cols + t * 64 + sg;    // keys 8j+sg, j=0..7
#pragma unroll
        for (int q = 0; q < 4; q++) {
            const float* src = gb + (size_t)cols[qbase + q] * 8192;
            float x0 = src[ct[0]]  * L2E, x1 = src[ct[8]]  * L2E;
            float x2 = src[ct[16]] * L2E, x3 = src[ct[24]] * L2E;
            float x4 = src[ct[32]] * L2E, x5 = src[ct[40]] * L2E;
            float x6 = src[ct[48]] * L2E, x7 = src[ct[56]] * L2E;
            uint4 v = make_uint4(packh2(x0, x1), packh2(x2, x3),
                                 packh2(x4, x5), packh2(x6, x7));
            __half* drow = g_bias + ((size_t)(b * 2048 + qbase + q)) * 2048;
            *(uint4*)&drow[t * 64 + sg * 8] = v;
        }
        return;
    }

    // ---------------- qkv role ----------------
    const int qid = grp * 3 + rem;  // 0..767
    const int bm = (qid / 12) * 128;
    const int bn = (qid % 12) * 128;
    const __half* __restrict__ A = g_qh;
    const __half* __restrict__ W = g_wh;
    const int tid = threadIdx.x;
    const int w = tid >> 5, lane = tid & 31;
    const int g = lane >> 2, c = lane & 3;
    const int wm = (w >> 2) * 64, wn = (w & 3) * 32;

    const int srow = tid >> 2, sh = (tid & 3) * 8;
    const int arow = wm + (lane & 15);
    const int acol8 = (lane >> 4) << 3;
    const int brow = wn + ((lane >> 4) << 3) + (lane & 7);
    const int bcol8 = ((lane >> 3) & 1) << 3;

    float acc[4][4][4];
#pragma unroll
    for (int nb = 0; nb < 4; nb++) {
        const int n = bn + wn + nb * 8 + 2 * c;
        const float b0 = bias[n], b1 = bias[n + 1];
#pragma unroll
        for (int mb = 0; mb < 4; mb++) {
            acc[mb][nb][0] = b0; acc[mb][nb][1] = b1;
            acc[mb][nb][2] = b0; acc[mb][nb][3] = b1;
        }
    }

    {
        unsigned sa = sptr(&As[0][0]), sb = sptr(&Bs[0][0]);
        cpa16(sa + (srow * 40 + sh) * 2, &A[(size_t)(bm + srow) * 512 + sh]);
        cpa16(sa + ((srow + 64) * 40 + sh) * 2, &A[(size_t)(bm + srow + 64) * 512 + sh]);
        cpa16(sb + (srow * 40 + sh) * 2, &W[(size_t)(bn + srow) * 512 + sh]);
        cpa16(sb + ((srow + 64) * 40 + sh) * 2, &W[(size_t)(bn + srow + 64) * 512 + sh]);
        CP_COMMIT();
    }

    for (int t = 0; t < 16; t++) {
        CP_WAIT0();
        __syncthreads();
        const int buf = t & 1;
        if (t + 1 < 16) {
            const int kt = (t + 1) * 32;
            unsigned sa = sptr(&As[buf ^ 1][0]), sb = sptr(&Bs[buf ^ 1][0]);
            cpa16(sa + (srow * 40 + sh) * 2, &A[(size_t)(bm + srow) * 512 + kt + sh]);
            cpa16(sa + ((srow + 64) * 40 + sh) * 2, &A[(size_t)(bm + srow + 64) * 512 + kt + sh]);
            cpa16(sb + (srow * 40 + sh) * 2, &W[(size_t)(bn + srow) * 512 + kt + sh]);
            cpa16(sb + ((srow + 64) * 40 + sh) * 2, &W[(size_t)(bn + srow + 64) * 512 + kt + sh]);
            CP_COMMIT();
        }
        const __half* as = As[buf];
        const __half* bs = Bs[buf];
#pragma unroll
        for (int ks = 0; ks < 2; ks++) {
            unsigned a[4][4];
#pragma unroll
            for (int mb = 0; mb < 4; mb++)
                ldsm4(a[mb][0], a[mb][1], a[mb][2], a[mb][3],
                      sptr(&as[(arow + mb * 16) * 40 + ks * 16 + acol8]));
            unsigned bb[4][2];
#pragma unroll
            for (int p = 0; p < 2; p++)
                ldsm4(bb[2 * p][0], bb[2 * p][1], bb[2 * p + 1][0], bb[2 * p + 1][1],
                      sptr(&bs[(brow + p * 16) * 40 + ks * 16 + bcol8]));
#pragma unroll
            for (int nb = 0; nb < 4; nb++)
#pragma unroll
                for (int mb = 0; mb < 4; mb++)
                    mma16(acc[mb][nb], a[mb], bb[nb][0], bb[nb][1]);
        }
    }

    const int part = bn >> 9;  // 0=Q 1=K 2=V (uniform per block)
    if (part < 2) {
        __half* dst = part ? g_k : g_q;
        const float sc = part ? 1.0f : 0.125f * L2E;
#pragma unroll
        for (int mb = 0; mb < 4; mb++) {
            const int m0 = bm + wm + mb * 16 + g;
            const int bb0 = m0 >> 11, s0 = m0 & 2047;
            const int bb1 = (m0 + 8) >> 11, s1 = (m0 + 8) & 2047;
#pragma unroll
            for (int nb = 0; nb < 4; nb++) {
                const int n = bn + wn + nb * 8 + 2 * c;
                const int h = (n >> 6) & 7;
                const int d = n & 63;
                *(unsigned*)&dst[((size_t)((bb0 * 8 + h) * 2048 + s0)) * 64 + d] =
                    packh2(acc[mb][nb][0] * sc, acc[mb][nb][1] * sc);
                *(unsigned*)&dst[((size_t)((bb1 * 8 + h) * 2048 + s1)) * 64 + d] =
                    packh2(acc[mb][nb][2] * sc, acc[mb][nb][3] * sc);
            }
        }
    } else {
#pragma unroll
        for (int mb = 0; mb < 4; mb++) {
            const int m0 = bm + wm + mb * 16 + g;
            const int bb0 = m0 >> 11, s0 = m0 & 2047;
            const int bb1 = (m0 + 8) >> 11, s1 = (m0 + 8) & 2047;
#pragma unroll
            for (int nb = 0; nb < 4; nb++) {
                const int n = bn + wn + nb * 8 + 2 * c;
                const int h = (n >> 6) & 7;
                const int d = n & 63;
                __half* p0 = &g_vt[((size_t)((bb0 * 8 + h) * 64 + d)) * 2048];
                __half* p1 = &g_vt[((size_t)((bb1 * 8 + h) * 64 + d)) * 2048];
                p0[s0] = __float2half_rn(acc[mb][nb][0]);
                p0[2048 + s0] = __float2half_rn(acc[mb][nb][1]);
                p1[s1] = __float2half_rn(acc[mb][nb][2]);
                p1[2048 + s1] = __float2half_rn(acc[mb][nb][3]);
            }
        }
    }
}

// ============================================================
// Kernel 3: flash attention.  128 threads / 4 warps, 32 q-rows per warp
// (2 m-blocks) -> each K/V ldsm feeds 4 mma: per-SM LDSM traffic halves
// vs the 8-warp/16-row version at identical HMMA count.
// Bias in fragment order (4 x LDG.128 per m-block).  Softmax: fixed max=0,
// f16x2 exp2, row sums via ones-mma.
// ============================================================
__global__ __launch_bounds__(128) void attn_kernel()
{
    __shared__ __align__(16) __half Ks[2][64 * 72];
    __shared__ __align__(16) __half Vts[2][64 * 72];

    const int qt = blockIdx.x, h = blockIdx.y, b = blockIdx.z;
    const int tid = threadIdx.x;
    const int w = tid >> 5, lane = tid & 31;
    const int g = lane >> 2, c = lane & 3;

    const size_t bh = (size_t)(b * 8 + h);
    const __half* Qg = g_q + bh * 2048 * 64;
    const __half* Kg = g_k + bh * 2048 * 64;
    const __half* Vtg = g_vt + bh * 64 * 2048;
    const __half* Bg = g_bias + ((size_t)b * 2048 + qt * 128) * 2048;

    const int lrow = ((lane >> 4) << 3) + (lane & 7);
    const int lcol8 = ((lane >> 3) & 1) << 3;

    // Q fragments: 2 m-blocks (rows 32w+16mb + {g, g+8})
    unsigned qA[2][4][4];
    {
        const int r0 = qt * 128 + 32 * w + g;
#pragma unroll
        for (int mb = 0; mb < 2; mb++)
#pragma unroll
            for (int kb = 0; kb < 4; kb++) {
                const __half* base = Qg + (size_t)(r0 + 16 * mb) * 64 + kb * 16 + 2 * c;
                qA[mb][kb][0] = *(const unsigned*)base;
                qA[mb][kb][1] = *(const unsigned*)(base + 8 * 64);
                qA[mb][kb][2] = *(const unsigned*)(base + 8);
                qA[mb][kb][3] = *(const unsigned*)(base + 8 * 64 + 8);
            }
    }

    float o[2][8][4];
#pragma unroll
    for (int mb = 0; mb < 2; mb++)
#pragma unroll
        for (int nb = 0; nb < 8; nb++)
#pragma unroll
            for (int i = 0; i < 4; i++) o[mb][nb][i] = 0.f;
    float lacc[2][4] = {{0.f, 0.f, 0.f, 0.f}, {0.f, 0.f, 0.f, 0.f}};

    // bias fragment bases per m-block (rows 32w+16mb+g / +8, slots 16c..)
    const __half* Bt[2][2];
#pragma unroll
    for (int mb = 0; mb < 2; mb++) {
        Bt[mb][0] = Bg + (size_t)(32 * w + 16 * mb + g) * 2048 + 16 * c;
        Bt[mb][1] = Bt[mb][0] + 8 * 2048;
    }

    // staging: 512 cpa16 tasks per buffer pair, 4 per thread per array
    {
        unsigned sk = sptr(&Ks[0][0]), sv = sptr(&Vts[0][0]);
#pragma unroll
        for (int j = 0; j < 4; j++) {
            const int idx = tid + 128 * j;
            const int row = idx >> 3, sh = (idx & 7) * 8;
            cpa16(sk + (row * 72 + sh) * 2, &Kg[(size_t)row * 64 + sh]);
            cpa16(sv + (row * 72 + sh) * 2, &Vtg[(size_t)row * 2048 + sh]);
        }
        CP_COMMIT();
    }

    for (int t = 0; t < 32; t++) {
        // bias -> score init (hoisted above pipeline wait)
        float s[2][8][4];
#pragma unroll
        for (int mb = 0; mb < 2; mb++) {
            uint4 lo0 = *(const uint4*)&Bt[mb][0][t * 64];
            uint4 hi0 = *(const uint4*)&Bt[mb][0][t * 64 + 8];
            uint4 lo1 = *(const uint4*)&Bt[mb][1][t * 64];
            uint4 hi1 = *(const uint4*)&Bt[mb][1][t * 64 + 8];
            const __half2* L0 = (const __half2*)&lo0;
            const __half2* H0 = (const __half2*)&hi0;
            const __half2* L1 = (const __half2*)&lo1;
            const __half2* H1 = (const __half2*)&hi1;
#pragma unroll
            for (int p = 0; p < 4; p++) {
                float2 a = __half22float2(L0[p]);
                float2 bq = __half22float2(H0[p]);
                float2 cc = __half22float2(L1[p]);
                float2 dd = __half22float2(H1[p]);
                s[mb][2 * p][0] = a.x;  s[mb][2 * p + 1][0] = a.y;
                s[mb][2 * p][1] = bq.x; s[mb][2 * p + 1][1] = bq.y;
                s[mb][2 * p][2] = cc.x; s[mb][2 * p + 1][2] = cc.y;
                s[mb][2 * p][3] = dd.x; s[mb][2 * p + 1][3] = dd.y;
            }
        }

        CP_WAIT0();
        __syncthreads();
        const int buf = t & 1;
        if (t + 1 < 32) {
            unsigned sk = sptr(&Ks[buf ^ 1][0]), sv = sptr(&Vts[buf ^ 1][0]);
            const __half* Kn = Kg + (size_t)(t + 1) * 64 * 64;
            const __half* Vn = Vtg + (size_t)(t + 1) * 64;
#pragma unroll
            for (int j = 0; j < 4; j++) {
                const int idx = tid + 128 * j;
                const int row = idx >> 3, sh = (idx & 7) * 8;
                cpa16(sk + (row * 72 + sh) * 2, &Kn[(size_t)row * 64 + sh]);
                cpa16(sv + (row * 72 + sh) * 2, &Vn[(size_t)row * 2048 + sh]);
            }
            CP_COMMIT();
        }
        const __half* ks_ = Ks[buf];
        const __half* vs_ = Vts[buf];

        // ---- GEMM1: one K ldsm feeds both m-blocks ----
#pragma unroll
        for (int kb = 0; kb < 4; kb++) {
#pragma unroll
            for (int j = 0; j < 4; j++) {
                unsigned b00, b01, b10, b11;
                ldsm4(b00, b01, b10, b11,
                      sptr(&ks_[(j * 16 + lrow) * 72 + kb * 16 + lcol8]));
                mma16(s[0][2 * j], qA[0][kb], b00, b01);
                mma16(s[0][2 * j + 1], qA[0][kb], b10, b11);
                mma16(s[1][2 * j], qA[1][kb], b00, b01);
                mma16(s[1][2 * j + 1], qA[1][kb], b10, b11);
            }
        }

        // ---- softmax: pack -> f16x2 exp2 -> P A-frags; row sums via ones-mma ----
        unsigned pa[2][4][4];
#pragma unroll
        for (int mb = 0; mb < 2; mb++) {
#pragma unroll
            for (int kb = 0; kb < 4; kb++) {
                pa[mb][kb][0] = h2exp2(packh2(s[mb][2 * kb][0], s[mb][2 * kb][1]));
                pa[mb][kb][1] = h2exp2(packh2(s[mb][2 * kb][2], s[mb][2 * kb][3]));
                pa[mb][kb][2] = h2exp2(packh2(s[mb][2 * kb + 1][0], s[mb][2 * kb + 1][1]));
                pa[mb][kb][3] = h2exp2(packh2(s[mb][2 * kb + 1][2], s[mb][2 * kb + 1][3]));
            }
#pragma unroll
            for (int kb = 0; kb < 4; kb++)
                mma16(lacc[mb], pa[mb][kb], ONES2, ONES2);
        }

        // ---- GEMM2: one V ldsm feeds both m-blocks ----
#pragma unroll
        for (int kb = 0; kb < 4; kb++) {
#pragma unroll
            for (int j = 0; j < 4; j++) {
                unsigned b00, b01, b10, b11;
                ldsm4(b00, b01, b10, b11,
                      sptr(&vs_[(j * 16 + lrow) * 72 + kb * 16 + lcol8]));
                mma16(o[0][2 * j], pa[0][kb], b00, b01);
                mma16(o[0][2 * j + 1], pa[0][kb], b10, b11);
                mma16(o[1][2 * j], pa[1][kb], b00, b01);
                mma16(o[1][2 * j + 1], pa[1][kb], b10, b11);
            }
        }
    }

#pragma unroll
    for (int mb = 0; mb < 2; mb++) {
        const float inv0 = 1.f / lacc[mb][0], inv1 = 1.f / lacc[mb][2];
        const int row0 = b * 2048 + qt * 128 + 32 * w + 16 * mb + g;
#pragma unroll
        for (int nb = 0; nb < 8; nb++) {
            const int d = h * 64 + nb * 8 + 2 * c;
            *(unsigned*)&g_ctxh[(size_t)row0 * 512 + d] =
                packh2(o[mb][nb][0] * inv0, o[mb][nb][1] * inv0);
            *(unsigned*)&g_ctxh[(size_t)(row0 + 8) * 512 + d] =
                packh2(o[mb][nb][2] * inv1, o[mb][nb][3] * inv1);
        }
    }
}

// ============================================================
// Kernel 4: output projection, fp16 mma + ldmatrix, BK=32, 2-stage (R11).
// ============================================================
__global__ __launch_bounds__(256) void out_gemm_kernel(
    const float* __restrict__ ob, float* __restrict__ C)
{
    __shared__ __align__(16) __half As[2][128 * 40];
    __shared__ __align__(16) __half Bs[2][128 * 40];
    const __half* __restrict__ A = g_ctxh;
    const __half* __restrict__ W = g_woh;
    const int bm = blockIdx.y * 128;
    const int bn = blockIdx.x * 128;
    const int tid = threadIdx.x;
    const int w = tid >> 5, lane = tid & 31;
    const int g = lane >> 2, c = lane & 3;
    const int wm = (w >> 2) * 64, wn = (w & 3) * 32;

    const int srow = tid >> 2, sh = (tid & 3) * 8;
    const int arow = wm + (lane & 15);
    const int acol8 = (lane >> 4) << 3;
    const int brow = wn + ((lane >> 4) << 3) + (lane & 7);
    const int bcol8 = ((lane >> 3) & 1) << 3;

    float acc[4][4][4];
#pragma unroll
    for (int nb = 0; nb < 4; nb++) {
        const int n = bn + wn + nb * 8 + 2 * c;
        const float b0 = ob[n], b1 = ob[n + 1];
#pragma unroll
        for (int mb = 0; mb < 4; mb++) {
            acc[mb][nb][0] = b0; acc[mb][nb][1] = b1;
            acc[mb][nb][2] = b0; acc[mb][nb][3] = b1;
        }
    }

    {
        unsigned sa = sptr(&As[0][0]), sb = sptr(&Bs[0][0]);
        cpa16(sa + (srow * 40 + sh) * 2, &A[(size_t)(bm + srow) * 512 + sh]);
        cpa16(sa + ((srow + 64) * 40 + sh) * 2, &A[(size_t)(bm + srow + 64) * 512 + sh]);
        cpa16(sb + (srow * 40 + sh) * 2, &W[(size_t)(bn + srow) * 512 + sh]);
        cpa16(sb + ((srow + 64) * 40 + sh) * 2, &W[(size_t)(bn + srow + 64) * 512 + sh]);
        CP_COMMIT();
    }

    for (int t = 0; t < 16; t++) {
        CP_WAIT0();
        __syncthreads();
        const int buf = t & 1;
        if (t + 1 < 16) {
            const int kt = (t + 1) * 32;
            unsigned sa = sptr(&As[buf ^ 1][0]), sb = sptr(&Bs[buf ^ 1][0]);
            cpa16(sa + (srow * 40 + sh) * 2, &A[(size_t)(bm + srow) * 512 + kt + sh]);
            cpa16(sa + ((srow + 64) * 40 + sh) * 2, &A[(size_t)(bm + srow + 64) * 512 + kt + sh]);
            cpa16(sb + (srow * 40 + sh) * 2, &W[(size_t)(bn + srow) * 512 + kt + sh]);
            cpa16(sb + ((srow + 64) * 40 + sh) * 2, &W[(size_t)(bn + srow + 64) * 512 + kt + sh]);
            CP_COMMIT();
        }
        const __half* as = As[buf];
        const __half* bs = Bs[buf];
#pragma unroll
        for (int ks = 0; ks < 2; ks++) {
            unsigned a[4][4];
#pragma unroll
            for (int mb = 0; mb < 4; mb++)
                ldsm4(a[mb][0], a[mb][1], a[mb][2], a[mb][3],
                      sptr(&as[(arow + mb * 16) * 40 + ks * 16 + acol8]));
            unsigned bb[4][2];
#pragma unroll
            for (int p = 0; p < 2; p++)
                ldsm4(bb[2 * p][0], bb[2 * p][1], bb[2 * p + 1][0], bb[2 * p + 1][1],
                      sptr(&bs[(brow + p * 16) * 40 + ks * 16 + bcol8]));
#pragma unroll
            for (int nb = 0; nb < 4; nb++)
#pragma unroll
                for (int mb = 0; mb < 4; mb++)
                    mma16(acc[mb][nb], a[mb], bb[nb][0], bb[nb][1]);
        }
    }

#pragma unroll
    for (int mb = 0; mb < 4; mb++) {
        const int m0 = bm + wm + mb * 16 + g;
#pragma unroll
        for (int nb = 0; nb < 4; nb++) {
            const int n = bn + wn + nb * 8 + 2 * c;
            *(float2*)&C[(size_t)m0 * 512 + n] =
                make_float2(acc[mb][nb][0], acc[mb][nb][1]);
            *(float2*)&C[(size_t)(m0 + 8) * 512 + n] =
                make_float2(acc[mb][nb][2], acc[mb][nb][3]);
        }
    }
}

// ============================================================
extern "C" void kernel_launch(void* const* d_in, const int* in_sizes, int n_in,
                              void* d_out, int out_size)
{
    const float* query = (const float*)d_in[0];
    const int*   gidx  = (const int*)d_in[1];
    const float* ipw   = (const float*)d_in[2];
    const float* ipb   = (const float*)d_in[3];
    const float* outw  = (const float*)d_in[4];
    const float* outb  = (const float*)d_in[5];
    const float* gbias = (const float*)d_in[6];
    float* out = (float*)d_out;

    cvt3_kernel<<<1280, 256>>>((const float4*)query, (const float4*)ipw,
                               (const float4*)outw);
    qkv_gather_kernel<<<2816, 256>>>(ipb, gidx, gbias);
    attn_kernel<<<dim3(16, 8, 4), 128>>>();
    out_gemm_kernel<<<dim3(4, 64), 256>>>(outb, out);
}